// round 1
// baseline (speedup 1.0000x reference)
#include <cuda_runtime.h>

// QuadraticConv2D: out[b,h,w,o] = sum_l sum_c F_l[b,h,w,c] * wk[l,c,o]
//   F: 45 quadratic (triu pairs of the 9 taps), 9 linear taps, 1 bias(=1).
// B=16, H=W=64, C=64, O=64, L=55.  Implicit GEMM M=65536, K=3520, N=64.

#define Bn 16
#define Hn 64
#define Wn 64
#define Cn 64
#define On 64
#define Ln 55

// tap index i in 0..8 -> (row i/3, col i%3); 255 = sentinel
__constant__ unsigned char c_IU[Ln] = {
    0,0,0,0,0,0,0,0,0,
    1,1,1,1,1,1,1,1,
    2,2,2,2,2,2,2,
    3,3,3,3,3,3,
    4,4,4,4,4,
    5,5,5,5,
    6,6,6,
    7,7,
    8,
    0,1,2,3,4,5,6,7,8,   // linear taps
    255                   // bias
};
__constant__ unsigned char c_JU[Ln] = {
    0,1,2,3,4,5,6,7,8,
    1,2,3,4,5,6,7,8,
    2,3,4,5,6,7,8,
    3,4,5,6,7,8,
    4,5,6,7,8,
    5,6,7,8,
    6,7,8,
    7,8,
    8,
    255,255,255,255,255,255,255,255,255,  // linear: no second factor
    255
};

// packed f32x2 helpers (Blackwell FFMA2 — PTX only)
__device__ __forceinline__ void fma2(unsigned long long& d,
                                     unsigned long long a,
                                     unsigned long long b) {
    asm("fma.rn.f32x2 %0, %1, %2, %0;" : "+l"(d) : "l"(a), "l"(b));
}
__device__ __forceinline__ unsigned long long bcast2(float v) {
    unsigned long long r;
    asm("mov.b64 %0, {%1, %1};" : "=l"(r) : "f"(v));
    return r;
}
__device__ __forceinline__ void unpack2(unsigned long long v, float& lo, float& hi) {
    asm("mov.b64 {%0, %1}, %2;" : "=f"(lo), "=f"(hi) : "l"(v));
}

// smem layout (floats):
//   xs : [3][66][64]  = 12672   (3 input rows + w-halo, channel-contiguous)
//   Fs : [64][68]     = 4352    (feature slab, Fs[c][m], padded)
//   Ws : [64][68]     = 4352    (weight slab,  Ws[c][o], padded)
#define XS_F 12672
#define FS_F 4352
#define SMEM_BYTES ((XS_F + 2 * FS_F) * 4)

__global__ __launch_bounds__(256, 2)
void qconv_kernel(const float* __restrict__ x,
                  const float* __restrict__ wk,
                  float* __restrict__ out) {
    extern __shared__ float smem[];
    float* xs = smem;
    float* Fs = smem + XS_F;
    float* Ws = Fs + FS_F;

    const int t  = threadIdx.x;
    const int bh = blockIdx.x;        // b*64 + h
    const int h  = bh & 63;
    const int b  = bh >> 6;

    // ---- load 3 input rows (with zero h-padding) ----
    #pragma unroll
    for (int r = 0; r < 3; ++r) {
        const int hh = h + r - 1;
        float4* d4 = (float4*)(xs + (r * 66 + 1) * 64);
        if (hh >= 0 && hh < Hn) {
            const float4* s4 = (const float4*)(x + ((b * Hn + hh) * Wn) * Cn);
            #pragma unroll
            for (int q = 0; q < 4; ++q) d4[t + q * 256] = s4[t + q * 256];
        } else {
            const float4 z = make_float4(0.f, 0.f, 0.f, 0.f);
            #pragma unroll
            for (int q = 0; q < 4; ++q) d4[t + q * 256] = z;
        }
    }
    // zero the w-halo columns (wcol 0 and 65) : 3 rows * 2 sides * 16 float4
    if (t < 96) {
        const int rr   = t >> 5;          // 0..2
        const int side = (t >> 4) & 1;    // 0..1
        const int c4   = t & 15;
        float4* p = (float4*)(xs + (rr * 66 + (side ? 65 : 0)) * 64 + c4 * 4);
        *p = make_float4(0.f, 0.f, 0.f, 0.f);
    }
    __syncthreads();

    // ---- GEMM thread mapping: 16x16 threads, 4x4 outputs each ----
    const int tx = t & 15;            // -> o
    const int ty = t >> 4;            // -> m (=w)
    const int m0 = ty * 4;
    const int o0 = tx * 4;

    // feature-fill mapping: lanes vary c (bank-friendly), each thread 4 m x 4 c
    const int cbase = t & 15;
    const int mf0   = (t >> 4) * 4;

    // accumulators: 4 m rows x 2 o-pairs, packed f32x2 (zero bits == (0.f,0.f))
    unsigned long long acc[4][2] = {{0ull, 0ull}, {0ull, 0ull}, {0ull, 0ull}, {0ull, 0ull}};

    for (int l = 0; l < Ln; ++l) {
        // --- stage W_l : wk[l, c, o] -> Ws[c][o] ---
        const float4* wsrc = (const float4*)(wk + l * (Cn * On));
        #pragma unroll
        for (int q = 0; q < 4; ++q) {
            const int idx = t + q * 256;      // float4 index 0..1023
            const int c   = idx >> 4;
            const int o4  = idx & 15;
            *(float4*)(Ws + c * 68 + o4 * 4) = wsrc[idx];
        }

        // --- build F_l[c][m] ---
        const int ii = c_IU[l];
        const int jj = c_JU[l];
        if (ii == 255) {
            const float4 one = make_float4(1.f, 1.f, 1.f, 1.f);
            #pragma unroll
            for (int q = 0; q < 4; ++q)
                *(float4*)(Fs + (cbase + q * 16) * 68 + mf0) = one;
        } else {
            const int ri = ii / 3, ci = ii % 3;
            const int offi = (ri * 66 + ci) * 64;
            if (jj == 255) {
                #pragma unroll
                for (int q = 0; q < 4; ++q) {
                    const int c = cbase + q * 16;
                    const float* pi = xs + offi + mf0 * 64 + c;
                    float4 f;
                    f.x = pi[0]; f.y = pi[64]; f.z = pi[128]; f.w = pi[192];
                    *(float4*)(Fs + c * 68 + mf0) = f;
                }
            } else {
                const int rj = jj / 3, cj = jj % 3;
                const int offj = (rj * 66 + cj) * 64;
                #pragma unroll
                for (int q = 0; q < 4; ++q) {
                    const int c = cbase + q * 16;
                    const float* pi = xs + offi + mf0 * 64 + c;
                    const float* pj = xs + offj + mf0 * 64 + c;
                    float4 f;
                    f.x = pi[0]   * pj[0];
                    f.y = pi[64]  * pj[64];
                    f.z = pi[128] * pj[128];
                    f.w = pi[192] * pj[192];
                    *(float4*)(Fs + c * 68 + mf0) = f;
                }
            }
        }
        __syncthreads();

        // --- slab GEMM: acc[m,o] += F[m,c] * W[c,o]  (64 K-steps) ---
        #pragma unroll 16
        for (int c = 0; c < Cn; ++c) {
            const float4 f = *(const float4*)(Fs + c * 68 + m0);
            const ulonglong2 wv = *(const ulonglong2*)(Ws + c * 68 + o0);
            const unsigned long long f0 = bcast2(f.x);
            const unsigned long long f1 = bcast2(f.y);
            const unsigned long long f2 = bcast2(f.z);
            const unsigned long long f3 = bcast2(f.w);
            fma2(acc[0][0], f0, wv.x); fma2(acc[0][1], f0, wv.y);
            fma2(acc[1][0], f1, wv.x); fma2(acc[1][1], f1, wv.y);
            fma2(acc[2][0], f2, wv.x); fma2(acc[2][1], f2, wv.y);
            fma2(acc[3][0], f3, wv.x); fma2(acc[3][1], f3, wv.y);
        }
        __syncthreads();
    }

    // ---- epilogue: out[(bh*64 + m)*64 + o] ----
    #pragma unroll
    for (int mi = 0; mi < 4; ++mi) {
        float4 v;
        unpack2(acc[mi][0], v.x, v.y);
        unpack2(acc[mi][1], v.z, v.w);
        *(float4*)(out + (bh * 64 + (m0 + mi)) * 64 + o0) = v;
    }
}

extern "C" void kernel_launch(void* const* d_in, const int* in_sizes, int n_in,
                              void* d_out, int out_size) {
    const float* x  = (const float*)d_in[0];
    const float* wk = (const float*)d_in[1];   // [1,1,55,64,64] contiguous
    float* out = (float*)d_out;

    cudaFuncSetAttribute(qconv_kernel,
                         cudaFuncAttributeMaxDynamicSharedMemorySize, SMEM_BYTES);
    qconv_kernel<<<Bn * Hn, 256, SMEM_BYTES>>>(x, wk, out);
}